// round 4
// baseline (speedup 1.0000x reference)
#include <cuda_runtime.h>
#include <cuda_bf16.h>

#define NUSERS 100000
#define NITEMS 50000
#define DIM 64
#define NNODES 150001            // users + items + padding row
#define ND 9600064               // NNODES * DIM
#define NEDGES 4800000
#define CAP 128                  // bucket capacity per row (Poisson(32) tail ~1e-40)

// ---------------- device scratch (static allocation — allowed) -------------
__device__ int   g_idx_stride;                    // 2 = int64 indices, 1 = int32
__device__ int   g_counts[NNODES + 15];           // padded for int4 zeroing
__device__ int2  g_bucket[(size_t)NNODES * CAP];  // .x = col, .y = bits(val)

// ---------------------------------------------------------------------------
// Detect index width: int64 little-endian values < 2^31 have zero high words.
// ---------------------------------------------------------------------------
__global__ void gcn_detect_kernel(const int* __restrict__ rows32,
                                  const int* __restrict__ cols32) {
    bool is64 = true;
    #pragma unroll
    for (int k = 0; k < 16; k++) {
        if (rows32[2 * k + 1] != 0) is64 = false;
        if (cols32[2 * k + 1] != 0) is64 = false;
    }
    g_idx_stride = is64 ? 2 : 1;
}

// ---------------------------------------------------------------------------
// Zero degree counters (every replay — cursors accumulate). int4 stores.
// ---------------------------------------------------------------------------
__global__ void gcn_zero_counts(void) {
    int i = blockIdx.x * blockDim.x + threadIdx.x;
    int n4 = (NNODES + 3) / 4;                     // 37501
    if (i < n4)
        reinterpret_cast<int4*>(g_counts)[i] = make_int4(0, 0, 0, 0);
}

// ---------------------------------------------------------------------------
// Single-pass scatter into fixed-capacity buckets. The ONLY pass over the
// edge arrays (95 MB from DRAM).
// ---------------------------------------------------------------------------
__global__ void gcn_scatter_kernel(const int* __restrict__ rowsw,
                                   const int* __restrict__ colsw,
                                   const float* __restrict__ vals) {
    int e = blockIdx.x * blockDim.x + threadIdx.x;
    if (e < NEDGES) {
        int stride = g_idx_stride;
        int r = rowsw[e * stride];
        int c = colsw[e * stride];
        float v = vals[e];
        int slot = atomicAdd(&g_counts[r], 1);
        if (slot < CAP)                            // never taken in practice
            g_bucket[(size_t)r * CAP + slot] = make_int2(c, __float_as_int(v));
    }
}

// ---------------------------------------------------------------------------
// ego = concat(user_emb, item_emb). h1..h3 fully overwritten — no zeroing.
// ---------------------------------------------------------------------------
__global__ void gcn_init_kernel(const float4* __restrict__ user_emb,
                                const float4* __restrict__ item_emb,
                                float4* __restrict__ ego) {
    const int n4 = ND / 4;
    const int u4 = NUSERS * (DIM / 4);
    int i = blockIdx.x * blockDim.x + threadIdx.x;
    if (i < n4)
        ego[i] = (i < u4) ? user_emb[i] : item_emb[i - u4];
}

// ---------------------------------------------------------------------------
// Bucket SpMM: one warp per node, float2 per lane (32 x 2 = 64 dims).
// 4-wide unroll; edge records loaded as broadcast int4 (2 edges per LDG.128).
// FUSE variant also emits hsum = ego + h1 + h2 + h3.
// ---------------------------------------------------------------------------
template <bool FUSE>
__global__ void gcn_spmm(const float* __restrict__ h,
                         float* __restrict__ y,
                         const float* __restrict__ ego,
                         const float* __restrict__ h1,
                         const float* __restrict__ h2,
                         float* __restrict__ hsum) {
    int warp = (blockIdx.x * blockDim.x + threadIdx.x) >> 5;
    if (warp >= NNODES) return;
    int lane = threadIdx.x & 31;
    int off = lane * 2;

    int cnt = g_counts[warp];
    if (cnt > CAP) cnt = CAP;                      // paranoia, never taken
    const int2* __restrict__ eb = g_bucket + (size_t)warp * CAP;
    const int4* __restrict__ eb4 = reinterpret_cast<const int4*>(eb);

    float ax = 0.f, ay = 0.f;
    int i = 0;
    for (; i + 4 <= cnt; i += 4) {
        int4 p = eb4[(i >> 1)];                    // edges i, i+1
        int4 q = eb4[(i >> 1) + 1];                // edges i+2, i+3
        float2 g0 = *reinterpret_cast<const float2*>(h + (size_t)p.x * DIM + off);
        float2 g1 = *reinterpret_cast<const float2*>(h + (size_t)p.z * DIM + off);
        float2 g2 = *reinterpret_cast<const float2*>(h + (size_t)q.x * DIM + off);
        float2 g3 = *reinterpret_cast<const float2*>(h + (size_t)q.z * DIM + off);
        float v0 = __int_as_float(p.y), v1 = __int_as_float(p.w);
        float v2 = __int_as_float(q.y), v3 = __int_as_float(q.w);
        ax += v0 * g0.x + v1 * g1.x + v2 * g2.x + v3 * g3.x;
        ay += v0 * g0.y + v1 * g1.y + v2 * g2.y + v3 * g3.y;
    }
    for (; i < cnt; i++) {
        int2 e0 = eb[i];
        float2 g0 = *reinterpret_cast<const float2*>(h + (size_t)e0.x * DIM + off);
        float v0 = __int_as_float(e0.y);
        ax += v0 * g0.x;
        ay += v0 * g0.y;
    }

    size_t base = (size_t)warp * DIM + off;
    *reinterpret_cast<float2*>(y + base) = make_float2(ax, ay);

    if (FUSE) {
        float2 a = *reinterpret_cast<const float2*>(ego + base);
        float2 b = *reinterpret_cast<const float2*>(h1 + base);
        float2 c = *reinterpret_cast<const float2*>(h2 + base);
        *reinterpret_cast<float2*>(hsum + base) =
            make_float2(a.x + b.x + c.x + ax, a.y + b.y + c.y + ay);
    }
}

// ---------------------------------------------------------------------------
// kernel_launch — graph-capturable, allocation-free.
// Output layout (out_size = 5*ND): [h_sum | ego | h1 | h2 | h3]
// ---------------------------------------------------------------------------
extern "C" void kernel_launch(void* const* d_in, const int* in_sizes, int n_in,
                              void* d_out, int out_size) {
    const float* user_emb = (const float*)d_in[0];
    const float* item_emb = (const float*)d_in[1];
    const float* vals     = (const float*)d_in[2];
    const int*   rowsw    = (const int*)d_in[3];
    const int*   colsw    = (const int*)d_in[4];

    float* out  = (float*)d_out;
    float* hsum = out;
    float* ego  = out + (size_t)ND;
    float* h1   = out + (size_t)2 * ND;
    float* h2   = out + (size_t)3 * ND;
    float* h3   = out + (size_t)4 * ND;

    gcn_detect_kernel<<<1, 1>>>(rowsw, colsw);
    gcn_zero_counts<<<(37501 + 255) / 256, 256>>>();
    gcn_scatter_kernel<<<(NEDGES + 255) / 256, 256>>>(rowsw, colsw, vals);

    {
        const int n4 = ND / 4;
        gcn_init_kernel<<<(n4 + 255) / 256, 256>>>(
            (const float4*)user_emb, (const float4*)item_emb, (float4*)ego);
    }

    {
        long long threads = (long long)NNODES * 32;
        unsigned grd = (unsigned)((threads + 255) / 256);
        gcn_spmm<false><<<grd, 256>>>(ego, h1, nullptr, nullptr, nullptr,
                                      nullptr);
        gcn_spmm<false><<<grd, 256>>>(h1, h2, nullptr, nullptr, nullptr,
                                      nullptr);
        gcn_spmm<true><<<grd, 256>>>(h2, h3, ego, h1, h2, hsum);
    }
}

// round 6
// speedup vs baseline: 1.3289x; 1.3289x over previous
#include <cuda_runtime.h>
#include <cuda_bf16.h>

#define NUSERS 100000
#define NITEMS 50000
#define DIM 64
#define NNODES 150001            // users + items + padding row
#define ND 9600064               // NNODES * DIM
#define NEDGES 4800000

#define SCAN_CHUNK 512
#define NB_SCAN ((NNODES + SCAN_CHUNK - 1) / SCAN_CHUNK)   // 293
#define NZERO4 ((NNODES + 3) / 4)                           // 37501 int4 stores

// ---------------- device scratch (static allocation — allowed) -------------
__device__ int   g_idx_stride;            // 2 if int64 indices, 1 if int32
__device__ int   g_counts[NNODES + 15];
__device__ int   g_rowptr[NNODES + 1];
__device__ int   g_cursor[NNODES];
__device__ int   g_blocksums[SCAN_CHUNK];
__device__ int2  g_edges[NEDGES];         // packed CSR records: col, bits(val)

// ---------------------------------------------------------------------------
// Launch 0: zero counters + (thread 0) detect index width.
// int64 LE values < 2^31 have zero high words; 32 zero checks => certain.
// ---------------------------------------------------------------------------
__global__ void gcn_zero_detect(const int* __restrict__ rows32,
                                const int* __restrict__ cols32) {
    int i = blockIdx.x * blockDim.x + threadIdx.x;
    if (i < NZERO4)
        reinterpret_cast<int4*>(g_counts)[i] = make_int4(0, 0, 0, 0);
    if (i == 0) {
        bool is64 = true;
        #pragma unroll
        for (int k = 0; k < 16; k++) {
            if (rows32[2 * k + 1] != 0) is64 = false;
            if (cols32[2 * k + 1] != 0) is64 = false;
        }
        g_idx_stride = is64 ? 2 : 1;
    }
}

// ---------------------------------------------------------------------------
// Launch 1: histogram of row degrees.
// ---------------------------------------------------------------------------
__global__ void gcn_hist_kernel(const int* __restrict__ rowsw) {
    int e = blockIdx.x * blockDim.x + threadIdx.x;
    if (e < NEDGES) {
        int r = rowsw[e * g_idx_stride];
        atomicAdd(&g_counts[r], 1);              // no return use -> RED
    }
}

// ---------------------------------------------------------------------------
// Launches 2-4: 3-phase exclusive scan.
// ---------------------------------------------------------------------------
__global__ void gcn_scan1(void) {
    __shared__ int s[SCAN_CHUNK];
    int t = threadIdx.x;
    int i = blockIdx.x * SCAN_CHUNK + t;
    s[t] = (i < NNODES) ? g_counts[i] : 0;
    __syncthreads();
    for (int off = SCAN_CHUNK / 2; off > 0; off >>= 1) {
        if (t < off) s[t] += s[t + off];
        __syncthreads();
    }
    if (t == 0) g_blocksums[blockIdx.x] = s[0];
}

__global__ void gcn_scan2(void) {
    __shared__ int s[SCAN_CHUNK];
    int t = threadIdx.x;
    int x = (t < NB_SCAN) ? g_blocksums[t] : 0;
    s[t] = x;
    __syncthreads();
    for (int off = 1; off < SCAN_CHUNK; off <<= 1) {
        int v = (t >= off) ? s[t - off] : 0;
        __syncthreads();
        s[t] += v;
        __syncthreads();
    }
    if (t < NB_SCAN) g_blocksums[t] = s[t] - x;   // exclusive
}

__global__ void gcn_scan3(void) {
    __shared__ int s[SCAN_CHUNK];
    int t = threadIdx.x;
    int i = blockIdx.x * SCAN_CHUNK + t;
    int x = (i < NNODES) ? g_counts[i] : 0;
    s[t] = x;
    __syncthreads();
    for (int off = 1; off < SCAN_CHUNK; off <<= 1) {
        int v = (t >= off) ? s[t - off] : 0;
        __syncthreads();
        s[t] += v;
        __syncthreads();
    }
    if (i < NNODES) {
        int excl = g_blocksums[blockIdx.x] + s[t] - x;
        g_rowptr[i] = excl;
        g_cursor[i] = excl;
    }
    if (i == 0) g_rowptr[NNODES] = NEDGES;
}

// ---------------------------------------------------------------------------
// Launch 5 (ncu samples this one): scatter edges into packed CSR slots.
// ---------------------------------------------------------------------------
__global__ void gcn_scatter_kernel(const int* __restrict__ rowsw,
                                   const int* __restrict__ colsw,
                                   const float* __restrict__ vals) {
    int e = blockIdx.x * blockDim.x + threadIdx.x;
    if (e < NEDGES) {
        int stride = g_idx_stride;
        int r = rowsw[e * stride];
        int c = colsw[e * stride];
        float v = vals[e];
        int pos = atomicAdd(&g_cursor[r], 1);
        g_edges[pos] = make_int2(c, __float_as_int(v));
    }
}

// ---------------------------------------------------------------------------
// Launch 6: ego = concat(user_emb, item_emb). h1..h3 fully overwritten later.
// ---------------------------------------------------------------------------
__global__ void gcn_init_kernel(const float4* __restrict__ user_emb,
                                const float4* __restrict__ item_emb,
                                float4* __restrict__ ego) {
    const int n4 = ND / 4;
    const int u4 = NUSERS * (DIM / 4);
    int i = blockIdx.x * blockDim.x + threadIdx.x;
    if (i < n4)
        ego[i] = (i < u4) ? user_emb[i] : item_emb[i - u4];
}

// ---------------------------------------------------------------------------
// Launches 7-9: CSR SpMM, warp per node, float2 per lane, 4-wide unroll
// (alignment-safe int2 edge loads, front-batched for MLP).
// FUSE variant also emits hsum = ego + h1 + h2 + h3.
// ---------------------------------------------------------------------------
template <bool FUSE>
__global__ void __launch_bounds__(256)
gcn_csr_spmm(const float* __restrict__ h,
             float* __restrict__ y,
             const float* __restrict__ ego,
             const float* __restrict__ h1,
             const float* __restrict__ h2,
             float* __restrict__ hsum) {
    int warp = (blockIdx.x * blockDim.x + threadIdx.x) >> 5;
    if (warp >= NNODES) return;
    int lane = threadIdx.x & 31;
    int off = lane * 2;

    int start = __ldg(&g_rowptr[warp]);
    int end   = __ldg(&g_rowptr[warp + 1]);

    float ax = 0.f, ay = 0.f;
    int i = start;
    for (; i + 4 <= end; i += 4) {
        int2 e0 = g_edges[i];
        int2 e1 = g_edges[i + 1];
        int2 e2 = g_edges[i + 2];
        int2 e3 = g_edges[i + 3];
        float2 g0 = *reinterpret_cast<const float2*>(h + (size_t)e0.x * DIM + off);
        float2 g1 = *reinterpret_cast<const float2*>(h + (size_t)e1.x * DIM + off);
        float2 g2 = *reinterpret_cast<const float2*>(h + (size_t)e2.x * DIM + off);
        float2 g3 = *reinterpret_cast<const float2*>(h + (size_t)e3.x * DIM + off);
        float v0 = __int_as_float(e0.y), v1 = __int_as_float(e1.y);
        float v2 = __int_as_float(e2.y), v3 = __int_as_float(e3.y);
        ax += v0 * g0.x + v1 * g1.x + v2 * g2.x + v3 * g3.x;
        ay += v0 * g0.y + v1 * g1.y + v2 * g2.y + v3 * g3.y;
    }
    for (; i < end; i++) {
        int2 e0 = g_edges[i];
        float2 g0 = *reinterpret_cast<const float2*>(h + (size_t)e0.x * DIM + off);
        float v0 = __int_as_float(e0.y);
        ax += v0 * g0.x;
        ay += v0 * g0.y;
    }

    size_t base = (size_t)warp * DIM + off;
    *reinterpret_cast<float2*>(y + base) = make_float2(ax, ay);

    if (FUSE) {
        float2 a = *reinterpret_cast<const float2*>(ego + base);
        float2 b = *reinterpret_cast<const float2*>(h1 + base);
        float2 c = *reinterpret_cast<const float2*>(h2 + base);
        *reinterpret_cast<float2*>(hsum + base) =
            make_float2(a.x + b.x + c.x + ax, a.y + b.y + c.y + ay);
    }
}

// ---------------------------------------------------------------------------
// kernel_launch — graph-capturable, allocation-free.
// Output layout (out_size = 5*ND): [h_sum | ego | h1 | h2 | h3]
// ---------------------------------------------------------------------------
extern "C" void kernel_launch(void* const* d_in, const int* in_sizes, int n_in,
                              void* d_out, int out_size) {
    const float* user_emb = (const float*)d_in[0];
    const float* item_emb = (const float*)d_in[1];
    const float* vals     = (const float*)d_in[2];
    const int*   rowsw    = (const int*)d_in[3];
    const int*   colsw    = (const int*)d_in[4];

    float* out  = (float*)d_out;
    float* hsum = out;
    float* ego  = out + (size_t)ND;
    float* h1   = out + (size_t)2 * ND;
    float* h2   = out + (size_t)3 * ND;
    float* h3   = out + (size_t)4 * ND;

    // 0  — grid must cover NZERO4 = 37501 int4 stores (R5 bug: divided by 4 twice)
    gcn_zero_detect<<<(NZERO4 + 255) / 256, 256>>>(rowsw, colsw);
    // 1
    gcn_hist_kernel<<<(NEDGES + 255) / 256, 256>>>(rowsw);
    // 2-4
    gcn_scan1<<<NB_SCAN, SCAN_CHUNK>>>();
    gcn_scan2<<<1, SCAN_CHUNK>>>();
    gcn_scan3<<<NB_SCAN, SCAN_CHUNK>>>();
    // 5 (profiled)
    gcn_scatter_kernel<<<(NEDGES + 255) / 256, 256>>>(rowsw, colsw, vals);
    // 6
    {
        const int n4 = ND / 4;
        gcn_init_kernel<<<(n4 + 255) / 256, 256>>>(
            (const float4*)user_emb, (const float4*)item_emb, (float4*)ego);
    }
    // 7-9
    {
        long long threads = (long long)NNODES * 32;
        unsigned grd = (unsigned)((threads + 255) / 256);
        gcn_csr_spmm<false><<<grd, 256>>>(ego, h1, nullptr, nullptr, nullptr,
                                          nullptr);
        gcn_csr_spmm<false><<<grd, 256>>>(h1, h2, nullptr, nullptr, nullptr,
                                          nullptr);
        gcn_csr_spmm<true><<<grd, 256>>>(h2, h3, ego, h1, h2, hsum);
    }
}